// round 2
// baseline (speedup 1.0000x reference)
#include <cuda_runtime.h>
#include <cuda_bf16.h>
#include <math_constants.h>

// Problem constants
#define Bb 8
#define Tt 2048
#define Cc 1024
#define Hh 64
#define NITEMS (Bb * (Tt / 64))   // 256 work items (b, i-block)

// Scratch: q = x @ Wq, [B, T, H] fp32 = 4 MB
__device__ float g_q[Bb * Tt * Hh];
__device__ int g_ctr;

// ---------------------------------------------------------------------------
// Kernel 1: q = x @ Wq    (M=16384, K=1024, N=64)
// 256 threads, BM=64, BN=64(full), BK=32; 4x4 register microtile.
// ---------------------------------------------------------------------------
__global__ void __launch_bounds__(256) qgemm_kernel(const float* __restrict__ x,
                                                    const float* __restrict__ w) {
    __shared__ float Xs[32][64];   // transposed: Xs[k][row]
    __shared__ float Ws[32][64];   // Ws[k][n]

    const int tid = threadIdx.x;
    if (blockIdx.x == 0 && tid == 0) g_ctr = 0;   // reset work counter for attn

    const int tx = tid & 15;        // 0..15 -> n group
    const int ty = tid >> 4;        // 0..15 -> row group
    const int r0 = blockIdx.x * 64;

    const int lr = tid >> 2;        // 0..63 (row for x loads)
    const int lc = tid & 3;         // 0..3  (float4 col group)

    float acc[4][4];
#pragma unroll
    for (int a = 0; a < 4; a++)
#pragma unroll
        for (int c = 0; c < 4; c++) acc[a][c] = 0.f;

    for (int kb = 0; kb < 32; kb++) {
        const int k0 = kb * 32;
        // load x tile [64 rows][32 k] transposed into Xs[k][row]
#pragma unroll
        for (int it = 0; it < 2; it++) {
            const int c4 = lc + it * 4;   // 0..7
            float4 v = *(const float4*)(x + (size_t)(r0 + lr) * Cc + k0 + c4 * 4);
            Xs[c4 * 4 + 0][lr] = v.x;
            Xs[c4 * 4 + 1][lr] = v.y;
            Xs[c4 * 4 + 2][lr] = v.z;
            Xs[c4 * 4 + 3][lr] = v.w;
        }
        // load w tile [32 k][64 n]
#pragma unroll
        for (int it = 0; it < 2; it++) {
            const int row = (tid >> 4) + it * 16;   // 0..31
            const int col = (tid & 15) * 4;
            *(float4*)&Ws[row][col] = *(const float4*)(w + (size_t)(k0 + row) * Hh + col);
        }
        __syncthreads();

#pragma unroll
        for (int k = 0; k < 32; k++) {
            const float4 qv = *(const float4*)&Xs[k][ty * 4];
            const float4 wv = *(const float4*)&Ws[k][tx * 4];
            const float qa[4] = {qv.x, qv.y, qv.z, qv.w};
            const float wc[4] = {wv.x, wv.y, wv.z, wv.w};
#pragma unroll
            for (int a = 0; a < 4; a++)
#pragma unroll
                for (int c = 0; c < 4; c++)
                    acc[a][c] = fmaf(qa[a], wc[c], acc[a][c]);
        }
        __syncthreads();
    }

#pragma unroll
    for (int a = 0; a < 4; a++) {
        float4 o = make_float4(acc[a][0], acc[a][1], acc[a][2], acc[a][3]);
        *(float4*)(g_q + (size_t)(r0 + ty * 4 + a) * Hh + tx * 4) = o;
    }
}

// ---------------------------------------------------------------------------
// Kernel 2: causal flash attention with skewed relative bias.
// scores[i,j] = (q_i . q_j + q_i . E[T-1-(i-j)]) * H^-0.5,  j <= i
// One work item = (b, 64-row i-block). BN = 64. Online softmax.
// Work stealing (heavy i-blocks first) for causal load balance.
// smem: Qs[64][68] Ks[64][68] Eb[127][68] Ps[64][68]  (dynamic, ~85 KB)
// ---------------------------------------------------------------------------
#define SMSTRIDE 68
#define ATTN_SMEM_FLOATS (SMSTRIDE * (64 * 3 + 127))
#define ATTN_SMEM_BYTES (ATTN_SMEM_FLOATS * 4)

__global__ void __launch_bounds__(256, 2) attn_kernel(const float* __restrict__ E,
                                                      float* __restrict__ out) {
    extern __shared__ float sm[];
    float* Qs = sm;                               // [64][68]
    float* Ks = sm + 64 * SMSTRIDE;               // [64][68]
    float* Eb = sm + 2 * 64 * SMSTRIDE;           // [127][68]
    float* Ps = sm + (2 * 64 + 127) * SMSTRIDE;   // [64][68]
    __shared__ int s_item;

    const int tid = threadIdx.x;
    const int tx = tid & 15;
    const int ty = tid >> 4;
    const int li0 = ty * 4;     // local i rows owned (4)
    const int lj0 = tx * 4;     // local j cols / h cols owned (4)
    const float SCALE = 0.125f; // 64^-0.5

    while (true) {
        __syncthreads();
        if (tid == 0) s_item = atomicAdd(&g_ctr, 1);
        __syncthreads();
        const int item = s_item;
        if (item >= NITEMS) return;

        const int b = item & 7;
        const int ib = 31 - (item >> 3);          // heavy (large i0) first
        const int i0 = ib * 64;
        const float* qb = g_q + (size_t)b * (Tt * Hh);

        // load Q tile
#pragma unroll
        for (int it = 0; it < 4; it++) {
            const int idx = tid + it * 256;       // < 1024 float4s
            const int row = idx >> 4, c4 = idx & 15;
            *(float4*)(Qs + row * SMSTRIDE + c4 * 4) =
                *(const float4*)(qb + (size_t)(i0 + row) * Hh + c4 * 4);
        }

        float O[4][4];
        float m[4], l[4];
#pragma unroll
        for (int a = 0; a < 4; a++) {
            m[a] = -CUDART_INF_F;
            l[a] = 0.f;
#pragma unroll
            for (int c = 0; c < 4; c++) O[a][c] = 0.f;
        }

        const int njb = ib + 1;
        for (int jb = 0; jb < njb; jb++) {
            const int j0 = jb * 64;
            const int diff = i0 - j0;             // >= 0

            // load K tile (= q rows j0..j0+63)
#pragma unroll
            for (int it = 0; it < 4; it++) {
                const int idx = tid + it * 256;
                const int row = idx >> 4, c4 = idx & 15;
                *(float4*)(Ks + row * SMSTRIDE + c4 * 4) =
                    *(const float4*)(qb + (size_t)(j0 + row) * Hh + c4 * 4);
            }
            // load E band: Eb[k] = E[T-1-d], d = (diff-63)+k, k=0..126
            const int dbase = diff - 63;
#pragma unroll
            for (int it = 0; it < 8; it++) {
                const int idx = tid + it * 256;
                if (idx < 127 * 16) {
                    const int k = idx >> 4, c4 = idx & 15;
                    const int d = dbase + k;
                    float4 v = make_float4(0.f, 0.f, 0.f, 0.f);
                    if (d >= 0 && d < Tt)
                        v = *(const float4*)(E + (size_t)(Tt - 1 - d) * Hh + c4 * 4);
                    *(float4*)(Eb + k * SMSTRIDE + c4 * 4) = v;
                }
            }
            __syncthreads();

            // --- scores: s[a][c] = sum_h Q[li][h] * (K[lj][h] + Eb[li-lj+63][h])
            float s[4][4];
#pragma unroll
            for (int a = 0; a < 4; a++)
#pragma unroll
                for (int c = 0; c < 4; c++) s[a][c] = 0.f;

#pragma unroll 4
            for (int h4 = 0; h4 < 16; h4++) {
                float4 qv[4], kv[4];
#pragma unroll
                for (int a = 0; a < 4; a++)
                    qv[a] = *(const float4*)(Qs + (li0 + a) * SMSTRIDE + h4 * 4);
#pragma unroll
                for (int c = 0; c < 4; c++)
                    kv[c] = *(const float4*)(Ks + (lj0 + c) * SMSTRIDE + h4 * 4);
#pragma unroll
                for (int a = 0; a < 4; a++) {
#pragma unroll
                    for (int c = 0; c < 4; c++) {
                        const float4 ev = *(const float4*)(
                            Eb + (li0 + a - lj0 - c + 63) * SMSTRIDE + h4 * 4);
                        float acc = s[a][c];
                        acc = fmaf(qv[a].x, kv[c].x + ev.x, acc);
                        acc = fmaf(qv[a].y, kv[c].y + ev.y, acc);
                        acc = fmaf(qv[a].z, kv[c].z + ev.z, acc);
                        acc = fmaf(qv[a].w, kv[c].w + ev.w, acc);
                        s[a][c] = acc;
                    }
                }
            }

            // --- online softmax per row
#pragma unroll
            for (int a = 0; a < 4; a++) {
                const int li = li0 + a;
                float sc[4];
                bool vld[4];
                float mt = -CUDART_INF_F;
#pragma unroll
                for (int c = 0; c < 4; c++) {
                    vld[c] = (lj0 + c) <= (li + diff);   // j <= i
                    sc[c] = s[a][c] * SCALE;
                    if (vld[c]) mt = fmaxf(mt, sc[c]);
                }
#pragma unroll
                for (int off = 8; off >= 1; off >>= 1)
                    mt = fmaxf(mt, __shfl_xor_sync(0xffffffffu, mt, off));
                const float mnew = fmaxf(m[a], mt);
                const float corr = __expf(m[a] - mnew);
                float rsum = 0.f;
                float p[4];
#pragma unroll
                for (int c = 0; c < 4; c++) {
                    p[c] = vld[c] ? __expf(sc[c] - mnew) : 0.f;
                    rsum += p[c];
                }
#pragma unroll
                for (int off = 8; off >= 1; off >>= 1)
                    rsum += __shfl_xor_sync(0xffffffffu, rsum, off);
                l[a] = l[a] * corr + rsum;
#pragma unroll
                for (int c = 0; c < 4; c++) O[a][c] *= corr;
                *(float4*)(Ps + li * SMSTRIDE + lj0) = make_float4(p[0], p[1], p[2], p[3]);
                m[a] = mnew;
            }
            __syncthreads();

            // --- O += P @ K   (V == K tile; h columns owned by tx)
#pragma unroll 4
            for (int j = 0; j < 64; j++) {
                const float4 kv = *(const float4*)(Ks + j * SMSTRIDE + tx * 4);
#pragma unroll
                for (int a = 0; a < 4; a++) {
                    const float pj = Ps[(li0 + a) * SMSTRIDE + j];
                    O[a][0] = fmaf(pj, kv.x, O[a][0]);
                    O[a][1] = fmaf(pj, kv.y, O[a][1]);
                    O[a][2] = fmaf(pj, kv.z, O[a][2]);
                    O[a][3] = fmaf(pj, kv.w, O[a][3]);
                }
            }
            __syncthreads();
        }

        // epilogue: out[b, i0+li, h] = O / l
        float* ob = out + ((size_t)b * Tt + i0) * Hh;
#pragma unroll
        for (int a = 0; a < 4; a++) {
            const float il = 1.0f / l[a];
            float4 o = make_float4(O[a][0] * il, O[a][1] * il, O[a][2] * il, O[a][3] * il);
            *(float4*)(ob + (li0 + a) * Hh + lj0) = o;
        }
    }
}

// ---------------------------------------------------------------------------
extern "C" void kernel_launch(void* const* d_in, const int* in_sizes, int n_in,
                              void* d_out, int out_size) {
    const float* x  = (const float*)d_in[0];   // [8, 2048, 1024]
    const float* Wq = (const float*)d_in[1];   // [1024, 64]
    const float* E  = (const float*)d_in[2];   // [2048, 64]
    float* out = (float*)d_out;                // [8, 2048, 64]

    cudaFuncSetAttribute(attn_kernel, cudaFuncAttributeMaxDynamicSharedMemorySize,
                         ATTN_SMEM_BYTES);

    qgemm_kernel<<<(Bb * Tt) / 64, 256>>>(x, Wq);        // also resets g_ctr
    attn_kernel<<<296, 256, ATTN_SMEM_BYTES>>>(E, out);  // work-stealing
}

// round 3
// speedup vs baseline: 4.6278x; 4.6278x over previous
#include <cuda_runtime.h>
#include <cstdint>

#define Bb 8
#define Tt 2048
#define Cc 1024
#define Hh 64
#define NITEMS 256   // (b, 64-row i-block) work items

__device__ float g_q[Bb * Tt * Hh];
__device__ int g_ctr;

// ---------------------------------------------------------------------------
// Kernel 1: q = x @ Wq    (M=16384, K=1024, N=64)  fp32 SIMT (exact)
// ---------------------------------------------------------------------------
__global__ void __launch_bounds__(256) qgemm_kernel(const float* __restrict__ x,
                                                    const float* __restrict__ w) {
    __shared__ float Xs[32][64];
    __shared__ float Ws[32][64];

    const int tid = threadIdx.x;
    if (blockIdx.x == 0 && tid == 0) g_ctr = 0;   // reset work counter for attn

    const int tx = tid & 15;
    const int ty = tid >> 4;
    const int r0 = blockIdx.x * 64;
    const int lr = tid >> 2;
    const int lc = tid & 3;

    float acc[4][4];
#pragma unroll
    for (int a = 0; a < 4; a++)
#pragma unroll
        for (int c = 0; c < 4; c++) acc[a][c] = 0.f;

    for (int kb = 0; kb < 32; kb++) {
        const int k0 = kb * 32;
#pragma unroll
        for (int it = 0; it < 2; it++) {
            const int c4 = lc + it * 4;
            float4 v = *(const float4*)(x + (size_t)(r0 + lr) * Cc + k0 + c4 * 4);
            Xs[c4 * 4 + 0][lr] = v.x;
            Xs[c4 * 4 + 1][lr] = v.y;
            Xs[c4 * 4 + 2][lr] = v.z;
            Xs[c4 * 4 + 3][lr] = v.w;
        }
#pragma unroll
        for (int it = 0; it < 2; it++) {
            const int row = (tid >> 4) + it * 16;
            const int col = (tid & 15) * 4;
            *(float4*)&Ws[row][col] = *(const float4*)(w + (size_t)(k0 + row) * Hh + col);
        }
        __syncthreads();

#pragma unroll
        for (int k = 0; k < 32; k++) {
            const float4 qv = *(const float4*)&Xs[k][ty * 4];
            const float4 wv = *(const float4*)&Ws[k][tx * 4];
            const float qa[4] = {qv.x, qv.y, qv.z, qv.w};
            const float wcv[4] = {wv.x, wv.y, wv.z, wv.w};
#pragma unroll
            for (int a = 0; a < 4; a++)
#pragma unroll
                for (int c = 0; c < 4; c++)
                    acc[a][c] = fmaf(qa[a], wcv[c], acc[a][c]);
        }
        __syncthreads();
    }

#pragma unroll
    for (int a = 0; a < 4; a++) {
        float4 o = make_float4(acc[a][0], acc[a][1], acc[a][2], acc[a][3]);
        *(float4*)(g_q + (size_t)(r0 + ty * 4 + a) * Hh + tx * 4) = o;
    }
}

// ---------------------------------------------------------------------------
// Kernel 2: causal flash attention + skewed rel bias via tf32 mma.sync.
//   s[i][j] = (q_i.q_j + q_i.E'[i-j]) * H^-0.5,  E'[d] = E[T-1-d],  j<=i
// Per (i-tile 64, j-tile 64):
//   R = Q @ Eband^T  (64x128 MMA) -> smem ; gather s += R[a][a-c+63]
//   S = Q @ K^T ; online softmax (cross-warp via smem reduce) ; O += P @ V
// 8 warps: warp (wr=wid&3, wc=wid>>2): rows mr=16*wr; S/O cols 32*wc; R d-half 64*wc.
// ---------------------------------------------------------------------------
#define KST 68            // stride of Qs/Ks/Eb/Ps
#define RST 132           // stride of Rs
#define OFF_QS 0
#define OFF_KS 4352       // 64*68
#define OFF_EB 8704
#define OFF_RS 17408      // 8704 + 128*68
#define OFF_PS 25856      // + 64*132
#define OFF_RM 30208      // + 64*68 : rowmax partials [2][64]
#define OFF_RL 30336      // rowsum partials [2][64]
#define SMEMF 30464
#define ATTN_SMEM_BYTES (SMEMF * 4)

__device__ __forceinline__ float cvt_tf32(float x) {
    uint32_t r;
    asm("cvt.rna.tf32.f32 %0, %1;" : "=r"(r) : "f"(x));
    return __uint_as_float(r);
}

__device__ __forceinline__ void mma8(float4& d, uint32_t a0, uint32_t a1,
                                     uint32_t a2, uint32_t a3,
                                     uint32_t b0, uint32_t b1) {
    asm volatile(
        "mma.sync.aligned.m16n8k8.row.col.f32.tf32.tf32.f32 "
        "{%0,%1,%2,%3}, {%4,%5,%6,%7}, {%8,%9}, {%0,%1,%2,%3};"
        : "+f"(d.x), "+f"(d.y), "+f"(d.z), "+f"(d.w)
        : "r"(a0), "r"(a1), "r"(a2), "r"(a3), "r"(b0), "r"(b1));
}

__global__ void __launch_bounds__(256) attn_mma(const float* __restrict__ E,
                                                float* __restrict__ out) {
    extern __shared__ float sm[];
    __shared__ int s_item;

    const int tid = threadIdx.x;
    const int wid = tid >> 5, lane = tid & 31;
    const int gid = lane >> 2, tig = lane & 3;
    const int wr = wid & 3, wc = wid >> 2;
    const int mr = wr * 16;       // warp row base (i local)
    const int nc = wc * 32;       // warp col base (j local for S, h for O)
    const int dc = wc * 64;       // warp d base for R
    const float SCALE = 0.125f;   // 64^-0.5

    while (true) {
        __syncthreads();
        if (tid == 0) s_item = atomicAdd(&g_ctr, 1);
        __syncthreads();
        const int item = s_item;
        if (item >= NITEMS) return;

        const int b = item & 7;
        const int ib = 31 - (item >> 3);       // heavy first
        const int i0 = ib * 64;
        const float* qb = g_q + (size_t)b * (Tt * Hh);

        // ---- load Q tile (tf32)
#pragma unroll
        for (int it = 0; it < 4; it++) {
            const int idx = tid + it * 256;            // 1024 float4
            const int row = idx >> 4, c4 = idx & 15;
            float4 v = *(const float4*)(qb + (size_t)(i0 + row) * Hh + c4 * 4);
            float* d = sm + OFF_QS + row * KST + c4 * 4;
            d[0] = cvt_tf32(v.x); d[1] = cvt_tf32(v.y);
            d[2] = cvt_tf32(v.z); d[3] = cvt_tf32(v.w);
        }

        float4 oacc[4] = {};
        float m0 = -1e30f, m1 = -1e30f, l0 = 0.f, l1 = 0.f;

        for (int jb = 0; jb <= ib; jb++) {
            const int j0 = jb * 64;
            const int diff = i0 - j0;
            const int dbase = diff - 63;

            __syncthreads();   // prev-iter consumers done (also orders Qs on iter 0)

            // ---- K tile (tf32)
#pragma unroll
            for (int it = 0; it < 4; it++) {
                const int idx = tid + it * 256;
                const int row = idx >> 4, c4 = idx & 15;
                float4 v = *(const float4*)(qb + (size_t)(j0 + row) * Hh + c4 * 4);
                float* d = sm + OFF_KS + row * KST + c4 * 4;
                d[0] = cvt_tf32(v.x); d[1] = cvt_tf32(v.y);
                d[2] = cvt_tf32(v.z); d[3] = cvt_tf32(v.w);
            }
            // ---- E band (rows k=0..126 hold E'[dbase+k]; row 127 zero)
#pragma unroll
            for (int it = 0; it < 8; it++) {
                const int idx = tid + it * 256;        // 2048 float4
                const int k = idx >> 4, c4 = idx & 15;
                const int d = dbase + k;
                float4 v = make_float4(0.f, 0.f, 0.f, 0.f);
                if (k < 127 && d >= 0)
                    v = *(const float4*)(E + (size_t)(Tt - 1 - d) * Hh + c4 * 4);
                float* ds = sm + OFF_EB + k * KST + c4 * 4;
                ds[0] = cvt_tf32(v.x); ds[1] = cvt_tf32(v.y);
                ds[2] = cvt_tf32(v.z); ds[3] = cvt_tf32(v.w);
            }
            __syncthreads();

            // ---- R = Q @ Eband^T  (warp: rows mr..+15, d cols dc..dc+63)
            float4 racc[8] = {};
#pragma unroll
            for (int kt = 0; kt < 8; kt++) {
                const int k0 = kt * 8;
                const uint32_t a0 = __float_as_uint(sm[OFF_QS + (mr + gid) * KST + k0 + tig]);
                const uint32_t a1 = __float_as_uint(sm[OFF_QS + (mr + gid + 8) * KST + k0 + tig]);
                const uint32_t a2 = __float_as_uint(sm[OFF_QS + (mr + gid) * KST + k0 + tig + 4]);
                const uint32_t a3 = __float_as_uint(sm[OFF_QS + (mr + gid + 8) * KST + k0 + tig + 4]);
#pragma unroll
                for (int nt = 0; nt < 8; nt++) {
                    const int dr = dc + nt * 8 + gid;
                    const uint32_t b0 = __float_as_uint(sm[OFF_EB + dr * KST + k0 + tig]);
                    const uint32_t b1 = __float_as_uint(sm[OFF_EB + dr * KST + k0 + tig + 4]);
                    mma8(racc[nt], a0, a1, a2, a3, b0, b1);
                }
            }
#pragma unroll
            for (int nt = 0; nt < 8; nt++) {          // store R (c-frag layout)
                const int col = dc + nt * 8 + 2 * tig;
                *(float2*)(sm + OFF_RS + (mr + gid) * RST + col) =
                    make_float2(racc[nt].x, racc[nt].y);
                *(float2*)(sm + OFF_RS + (mr + gid + 8) * RST + col) =
                    make_float2(racc[nt].z, racc[nt].w);
            }

            // ---- S = Q @ K^T  (warp: rows mr..+15, cols nc..+31)
            float4 sacc[4] = {};
#pragma unroll
            for (int kt = 0; kt < 8; kt++) {
                const int k0 = kt * 8;
                const uint32_t a0 = __float_as_uint(sm[OFF_QS + (mr + gid) * KST + k0 + tig]);
                const uint32_t a1 = __float_as_uint(sm[OFF_QS + (mr + gid + 8) * KST + k0 + tig]);
                const uint32_t a2 = __float_as_uint(sm[OFF_QS + (mr + gid) * KST + k0 + tig + 4]);
                const uint32_t a3 = __float_as_uint(sm[OFF_QS + (mr + gid + 8) * KST + k0 + tig + 4]);
#pragma unroll
                for (int nt = 0; nt < 4; nt++) {
                    const int jr = nc + nt * 8 + gid;
                    const uint32_t b0 = __float_as_uint(sm[OFF_KS + jr * KST + k0 + tig]);
                    const uint32_t b1 = __float_as_uint(sm[OFF_KS + jr * KST + k0 + tig + 4]);
                    mma8(sacc[nt], a0, a1, a2, a3, b0, b1);
                }
            }
            __syncthreads();   // Rs visible to all warps

            // ---- gather rel bias + scale + causal mask; warp-partial rowmax
            const int r0l = mr + gid, r1l = r0l + 8;
            float sv[4][4];
            float mt0 = -1e30f, mt1 = -1e30f;
#pragma unroll
            for (int nt = 0; nt < 4; nt++) {
                const int c0 = nc + nt * 8 + 2 * tig, c1 = c0 + 1;
                float s00 = (sacc[nt].x + sm[OFF_RS + r0l * RST + (r0l - c0 + 63)]) * SCALE;
                float s01 = (sacc[nt].y + sm[OFF_RS + r0l * RST + (r0l - c1 + 63)]) * SCALE;
                float s10 = (sacc[nt].z + sm[OFF_RS + r1l * RST + (r1l - c0 + 63)]) * SCALE;
                float s11 = (sacc[nt].w + sm[OFF_RS + r1l * RST + (r1l - c1 + 63)]) * SCALE;
                if (c0 > r0l + diff) s00 = -1e30f;
                if (c1 > r0l + diff) s01 = -1e30f;
                if (c0 > r1l + diff) s10 = -1e30f;
                if (c1 > r1l + diff) s11 = -1e30f;
                sv[nt][0] = s00; sv[nt][1] = s01; sv[nt][2] = s10; sv[nt][3] = s11;
                mt0 = fmaxf(mt0, fmaxf(s00, s01));
                mt1 = fmaxf(mt1, fmaxf(s10, s11));
            }
            mt0 = fmaxf(mt0, __shfl_xor_sync(0xffffffffu, mt0, 1));
            mt0 = fmaxf(mt0, __shfl_xor_sync(0xffffffffu, mt0, 2));
            mt1 = fmaxf(mt1, __shfl_xor_sync(0xffffffffu, mt1, 1));
            mt1 = fmaxf(mt1, __shfl_xor_sync(0xffffffffu, mt1, 2));
            if (tig == 0) {
                sm[OFF_RM + wc * 64 + r0l] = mt0;
                sm[OFF_RM + wc * 64 + r1l] = mt1;
            }
            __syncthreads();
            const float mn0 = fmaxf(m0, fmaxf(sm[OFF_RM + r0l], sm[OFF_RM + 64 + r0l]));
            const float mn1 = fmaxf(m1, fmaxf(sm[OFF_RM + r1l], sm[OFF_RM + 64 + r1l]));

            // ---- P = exp(s - m)  (tf32-rounded; sums use the rounded values)
            float sum0 = 0.f, sum1 = 0.f;
#pragma unroll
            for (int nt = 0; nt < 4; nt++) {
                const int c0 = nc + nt * 8 + 2 * tig;
                const float p00 = cvt_tf32(__expf(sv[nt][0] - mn0));
                const float p01 = cvt_tf32(__expf(sv[nt][1] - mn0));
                const float p10 = cvt_tf32(__expf(sv[nt][2] - mn1));
                const float p11 = cvt_tf32(__expf(sv[nt][3] - mn1));
                sum0 += p00 + p01;
                sum1 += p10 + p11;
                *(float2*)(sm + OFF_PS + r0l * KST + c0) = make_float2(p00, p01);
                *(float2*)(sm + OFF_PS + r1l * KST + c0) = make_float2(p10, p11);
            }
            sum0 += __shfl_xor_sync(0xffffffffu, sum0, 1);
            sum0 += __shfl_xor_sync(0xffffffffu, sum0, 2);
            sum1 += __shfl_xor_sync(0xffffffffu, sum1, 1);
            sum1 += __shfl_xor_sync(0xffffffffu, sum1, 2);
            if (tig == 0) {
                sm[OFF_RL + wc * 64 + r0l] = sum0;
                sm[OFF_RL + wc * 64 + r1l] = sum1;
            }
            const float corr0 = __expf(m0 - mn0);
            const float corr1 = __expf(m1 - mn1);
            m0 = mn0; m1 = mn1;
#pragma unroll
            for (int nt = 0; nt < 4; nt++) {
                oacc[nt].x *= corr0; oacc[nt].y *= corr0;
                oacc[nt].z *= corr1; oacc[nt].w *= corr1;
            }
            __syncthreads();   // Ps + rowsum partials visible
            l0 = l0 * corr0 + sm[OFF_RL + r0l] + sm[OFF_RL + 64 + r0l];
            l1 = l1 * corr1 + sm[OFF_RL + r1l] + sm[OFF_RL + 64 + r1l];

            // ---- O += P @ V   (V = K tile; warp: rows mr..+15, h cols nc..+31)
#pragma unroll
            for (int kt = 0; kt < 8; kt++) {
                const int k0 = kt * 8;
                const uint32_t a0 = __float_as_uint(sm[OFF_PS + (mr + gid) * KST + k0 + tig]);
                const uint32_t a1 = __float_as_uint(sm[OFF_PS + (mr + gid + 8) * KST + k0 + tig]);
                const uint32_t a2 = __float_as_uint(sm[OFF_PS + (mr + gid) * KST + k0 + tig + 4]);
                const uint32_t a3 = __float_as_uint(sm[OFF_PS + (mr + gid + 8) * KST + k0 + tig + 4]);
#pragma unroll
                for (int nt = 0; nt < 4; nt++) {
                    const int hcol = nc + nt * 8 + gid;
                    const uint32_t b0 = __float_as_uint(sm[OFF_KS + (k0 + tig) * KST + hcol]);
                    const uint32_t b1 = __float_as_uint(sm[OFF_KS + (k0 + tig + 4) * KST + hcol]);
                    mma8(oacc[nt], a0, a1, a2, a3, b0, b1);
                }
            }
        }

        // ---- epilogue: out = O / l
        const float inv0 = 1.0f / l0, inv1 = 1.0f / l1;
        float* ob = out + ((size_t)b * Tt + i0) * Hh;
#pragma unroll
        for (int nt = 0; nt < 4; nt++) {
            const int col = nc + nt * 8 + 2 * tig;
            *(float2*)(ob + (size_t)(mr + gid) * Hh + col) =
                make_float2(oacc[nt].x * inv0, oacc[nt].y * inv0);
            *(float2*)(ob + (size_t)(mr + gid + 8) * Hh + col) =
                make_float2(oacc[nt].z * inv1, oacc[nt].w * inv1);
        }
    }
}

// ---------------------------------------------------------------------------
extern "C" void kernel_launch(void* const* d_in, const int* in_sizes, int n_in,
                              void* d_out, int out_size) {
    const float* x  = (const float*)d_in[0];   // [8, 2048, 1024]
    const float* Wq = (const float*)d_in[1];   // [1024, 64]
    const float* E  = (const float*)d_in[2];   // [2048, 64]
    float* out = (float*)d_out;                // [8, 2048, 64]

    cudaFuncSetAttribute(attn_mma, cudaFuncAttributeMaxDynamicSharedMemorySize,
                         ATTN_SMEM_BYTES);

    qgemm_kernel<<<(Bb * Tt) / 64, 256>>>(x, Wq);       // also resets g_ctr
    attn_mma<<<148, 256, ATTN_SMEM_BYTES>>>(E, out);    // persistent + work-steal
}